// round 14
// baseline (speedup 1.0000x reference)
#include <cuda_runtime.h>
#include <cuda_fp16.h>
#include <cstdint>
#include <math.h>

#define D_MODEL  1024
#define N_HEADS  16
#define HEAD_DIM 64
#define B_SIZE   4
#define T_SEQ    2048
#define M_ROWS   (B_SIZE * T_SEQ)   // 8192
#define KDIM     1024

#define NEG_INF  (__int_as_float(0xff800000))

// ---------------------------------------------------------------------------
// Scratch (device globals: no allocations allowed)
// ---------------------------------------------------------------------------
__device__ __half g_xh[(size_t)M_ROWS * D_MODEL];
__device__ __half g_wqh[(size_t)D_MODEL * D_MODEL];
__device__ __half g_wkh[(size_t)D_MODEL * D_MODEL];
__device__ __half g_wvh[(size_t)D_MODEL * D_MODEL];
__device__ __half g_woh[(size_t)D_MODEL * D_MODEL];

__device__ __half g_qh[(size_t)M_ROWS * D_MODEL];   // (B,H,T,hd), pre-scaled by 0.125*log2e
__device__ __half g_kh[(size_t)M_ROWS * D_MODEL];
__device__ __half g_vh[(size_t)M_ROWS * D_MODEL];
__device__ __half g_ah[(size_t)M_ROWS * D_MODEL];   // attn out (B,T,D)

// ---------------------------------------------------------------------------
// PTX helpers (base ISA only)
// ---------------------------------------------------------------------------
__device__ __forceinline__ uint32_t smem_to_u32(const void* p) {
    uint32_t a;
    asm("{ .reg .u64 t; cvta.to.shared.u64 t, %1; cvt.u32.u64 %0, t; }"
        : "=r"(a) : "l"(p));
    return a;
}

#define CP_ASYNC16(dst, src) \
    asm volatile("cp.async.cg.shared.global [%0], [%1], 16;" :: "r"(dst), "l"(src))
#define CP_COMMIT() asm volatile("cp.async.commit_group;" ::: "memory")
#define CP_WAIT(n)  asm volatile("cp.async.wait_group %0;" :: "n"(n) : "memory")

#define LDSM_X4(r0, r1, r2, r3, addr) \
    asm volatile("ldmatrix.sync.aligned.m8n8.x4.shared.b16 {%0,%1,%2,%3}, [%4];" \
                 : "=r"(r0), "=r"(r1), "=r"(r2), "=r"(r3) : "r"(addr))
#define LDSM_X4_T(r0, r1, r2, r3, addr) \
    asm volatile("ldmatrix.sync.aligned.m8n8.x4.trans.shared.b16 {%0,%1,%2,%3}, [%4];" \
                 : "=r"(r0), "=r"(r1), "=r"(r2), "=r"(r3) : "r"(addr))

#define MMA_F16(c, a, b) \
    asm volatile("mma.sync.aligned.m16n8k16.row.col.f32.f16.f16.f32 " \
                 "{%0,%1,%2,%3}, {%4,%5,%6,%7}, {%8,%9}, {%0,%1,%2,%3};" \
                 : "+f"((c)[0]), "+f"((c)[1]), "+f"((c)[2]), "+f"((c)[3]) \
                 : "r"((a)[0]), "r"((a)[1]), "r"((a)[2]), "r"((a)[3]), \
                   "r"((b)[0]), "r"((b)[1]))

// pack two fp32 -> f16x2 reg: low half = x, high half = y
__device__ __forceinline__ uint32_t pack_f16(float x, float y) {
    uint32_t r;
    asm("cvt.rn.f16x2.f32 %0, %1, %2;" : "=r"(r) : "f"(y), "f"(x));
    return r;
}
// hardware exp2
__device__ __forceinline__ float ex2(float x) {
    float r;
    asm("ex2.approx.ftz.f32 %0, %1;" : "=f"(r) : "f"(x));
    return r;
}

// ---------------------------------------------------------------------------
// fp32 -> f16 converters, 4 float4 per thread for MLP.
// n4 must be divisible by 4 (all our sizes are).
// ---------------------------------------------------------------------------
__global__ void __launch_bounds__(256) cvt_f16(const float* __restrict__ x,
                                               __half* __restrict__ hi, int n4)
{
    int i0 = (blockIdx.x * blockDim.x + threadIdx.x) * 4;
    if (i0 >= n4) return;
    float4 v0 = ((const float4*)x)[i0 + 0];
    float4 v1 = ((const float4*)x)[i0 + 1];
    float4 v2 = ((const float4*)x)[i0 + 2];
    float4 v3 = ((const float4*)x)[i0 + 3];
    uint32_t* hp = (uint32_t*)hi;
    hp[i0 * 2 + 0] = pack_f16(v0.x, v0.y);
    hp[i0 * 2 + 1] = pack_f16(v0.z, v0.w);
    hp[i0 * 2 + 2] = pack_f16(v1.x, v1.y);
    hp[i0 * 2 + 3] = pack_f16(v1.z, v1.w);
    hp[i0 * 2 + 4] = pack_f16(v2.x, v2.y);
    hp[i0 * 2 + 5] = pack_f16(v2.z, v2.w);
    hp[i0 * 2 + 6] = pack_f16(v3.x, v3.y);
    hp[i0 * 2 + 7] = pack_f16(v3.z, v3.w);
}

struct CvtArgs {
    const float* src[4];
    __half* hi[4];
};
__global__ void __launch_bounds__(256) cvt_f16m(const CvtArgs a, int n4)
{
    const int z = blockIdx.z;
    const float* x = a.src[z];
    __half* hi = a.hi[z];
    int i0 = (blockIdx.x * blockDim.x + threadIdx.x) * 4;
    if (i0 >= n4) return;
    float4 v0 = ((const float4*)x)[i0 + 0];
    float4 v1 = ((const float4*)x)[i0 + 1];
    float4 v2 = ((const float4*)x)[i0 + 2];
    float4 v3 = ((const float4*)x)[i0 + 3];
    uint32_t* hp = (uint32_t*)hi;
    hp[i0 * 2 + 0] = pack_f16(v0.x, v0.y);
    hp[i0 * 2 + 1] = pack_f16(v0.z, v0.w);
    hp[i0 * 2 + 2] = pack_f16(v1.x, v1.y);
    hp[i0 * 2 + 3] = pack_f16(v1.z, v1.w);
    hp[i0 * 2 + 4] = pack_f16(v2.x, v2.y);
    hp[i0 * 2 + 5] = pack_f16(v2.z, v2.w);
    hp[i0 * 2 + 6] = pack_f16(v3.x, v3.y);
    hp[i0 * 2 + 7] = pack_f16(v3.z, v3.w);
}

// ---------------------------------------------------------------------------
// mma.sync 1-pass f16 GEMM:  C(8192x1024) = A @ W^T   (unchanged)
// ---------------------------------------------------------------------------
#define BM 128
#define BN 128
#define BK 32
#define NKI (KDIM / BK)          // 32
#define SKP 40                   // smem row stride in f16
#define TILE_B (BM * SKP * 2)    // 10240 bytes per tile
#define STAGE_B (2 * TILE_B)     // Ah, Bh
#define GEMM_SMEM_BYTES (3 * STAGE_B)

struct GemmArgs {
    const __half* Ah;
    const __half* Bh[3];
    float*  Cf[3];
    __half* Ch[3];
    float   scale[3];
    int     split;      // 1 -> (B,H,T,hd) output layout
};

__global__ void __launch_bounds__(256) gemm_f16(const GemmArgs args)
{
    extern __shared__ char smem_raw[];
    const uint32_t smem = smem_to_u32(smem_raw);

    const int z = blockIdx.z;
    const __half* Ah = args.Ah;
    const __half* Bh = args.Bh[z];

    const int tid  = threadIdx.x;
    const int wid  = tid >> 5;
    const int lane = tid & 31;
    const int row0 = blockIdx.y * BM;
    const int col0 = blockIdx.x * BN;

    const int m0 = (wid & 1) * 64;
    const int n0 = (wid >> 1) * 32;

    const int lrow   = tid >> 1;
    const int lcol16 = (tid & 1) * 16;
    const size_t a_goff = (size_t)(row0 + lrow) * KDIM + lcol16;
    const size_t b_goff = (size_t)(col0 + lrow) * KDIM + lcol16;
    const uint32_t sdst0 = (uint32_t)(lrow * SKP + lcol16) * 2;

    auto load_stage = [&](int stage, int kt) {
        const uint32_t sb = smem + (uint32_t)stage * STAGE_B;
        const size_t ko = (size_t)kt * BK;
        const char* s0 = (const char*)(Ah + a_goff + ko);
        const char* s2 = (const char*)(Bh + b_goff + ko);
#pragma unroll
        for (int c = 0; c < 2; c++) {
            CP_ASYNC16(sb + 0 * TILE_B + sdst0 + c * 16, s0 + c * 16);
            CP_ASYNC16(sb + 1 * TILE_B + sdst0 + c * 16, s2 + c * 16);
        }
        CP_COMMIT();
    };

    const uint32_t a_ld = (uint32_t)((m0 + (lane & 15)) * SKP + (lane >> 4) * 8) * 2;
    const uint32_t b_ld = (uint32_t)((n0 + (lane & 7) + ((lane >> 4) << 3)) * SKP
                                     + (((lane >> 3) & 1) << 3)) * 2;

    float acc[4][4][4];
#pragma unroll
    for (int i = 0; i < 4; i++)
#pragma unroll
        for (int j = 0; j < 4; j++)
#pragma unroll
            for (int r = 0; r < 4; r++) acc[i][j][r] = 0.f;

    load_stage(0, 0);
    load_stage(1, 1);

    for (int kt = 0; kt < NKI; kt++) {
        if (kt + 1 < NKI) { CP_WAIT(1); } else { CP_WAIT(0); }
        __syncthreads();
        if (kt + 2 < NKI) load_stage((kt + 2) % 3, kt + 2);

        const uint32_t sb  = smem + (uint32_t)(kt % 3) * STAGE_B;
        const uint32_t sAh = sb + 0 * TILE_B;
        const uint32_t sBh = sb + 1 * TILE_B;

#pragma unroll
        for (int ks = 0; ks < 2; ks++) {
            const uint32_t kso = (uint32_t)(ks * 16) * 2;
            uint32_t fAh[4][4];
            uint32_t fBh[4][2];
#pragma unroll
            for (int am = 0; am < 4; am++) {
                const uint32_t off = (uint32_t)(am * 16 * SKP) * 2 + kso;
                LDSM_X4(fAh[am][0], fAh[am][1], fAh[am][2], fAh[am][3], sAh + a_ld + off);
            }
#pragma unroll
            for (int bp = 0; bp < 2; bp++) {
                const uint32_t off = (uint32_t)(bp * 16 * SKP) * 2 + kso;
                LDSM_X4(fBh[2 * bp][0], fBh[2 * bp][1], fBh[2 * bp + 1][0], fBh[2 * bp + 1][1],
                        sBh + b_ld + off);
            }
#pragma unroll
            for (int am = 0; am < 4; am++)
#pragma unroll
                for (int na = 0; na < 4; na++)
                    MMA_F16(acc[am][na], fAh[am], fBh[na]);
        }
    }

    float* Cf = args.Cf[z];
    __half* Ch = args.Ch[z];
    const float scale = args.scale[z];
    const int split = args.split;

    const int lr4 = lane >> 2;
    const int lc2 = (lane & 3) * 2;
#pragma unroll
    for (int am = 0; am < 4; am++) {
        const int mA = row0 + m0 + am * 16 + lr4;
#pragma unroll
        for (int na = 0; na < 4; na++) {
            const int n = col0 + n0 + na * 8 + lc2;
#pragma unroll
            for (int half_ = 0; half_ < 2; half_++) {
                const int m = mA + half_ * 8;
                float vx = acc[am][na][half_ * 2 + 0] * scale;
                float vy = acc[am][na][half_ * 2 + 1] * scale;
                size_t idx;
                if (split) {
                    const int bb = m >> 11, t = m & 2047;
                    const int hh = n >> 6, d = n & 63;
                    idx = (((size_t)bb * N_HEADS + hh) * T_SEQ + t) * HEAD_DIM + d;
                } else {
                    idx = (size_t)m * D_MODEL + n;
                }
                if (Cf) *(float2*)&Cf[idx] = make_float2(vx, vy);
                if (Ch) *(uint32_t*)&Ch[idx] = pack_f16(vx, vy);
            }
        }
    }
}

// ---------------------------------------------------------------------------
// mma.sync flash attention, causal. BQ=128 (8 warps x m16), BKV=64, 256 thr.
// exp2-domain softmax; 3-stage pipeline, one barrier per tile.
// Warps 0-3 skip the final (fully-masked) diagonal tile — exact identity.
// ---------------------------------------------------------------------------
#define AST 72                        // smem row stride (f16 elems)
#define ATILE_B (64 * AST * 2)        // 9216 bytes (64-row K/V tile)
#define QTILE_B (128 * AST * 2)       // 18432 bytes (128-row Q tile)
#define ASMEM_BYTES (QTILE_B + 6 * ATILE_B)   // Q + 3 stages x {Kh,Vh}

__global__ void __launch_bounds__(256, 2) attn_mma(
    const __half* __restrict__ qh,
    const __half* __restrict__ kh,
    const __half* __restrict__ vh,
    __half* __restrict__ oh)
{
    extern __shared__ char smem_raw[];
    const uint32_t smem = smem_to_u32(smem_raw);
    const uint32_t sQh = smem;
    const uint32_t sKV = smem + QTILE_B;

    const int tid  = threadIdx.x;
    const int wid  = tid >> 5;
    const int lane = tid & 31;
    const int qb = gridDim.x - 1 - blockIdx.x;   // heaviest tiles first
    const int h = blockIdx.y, b = blockIdx.z;
    const size_t head_elem = ((size_t)b * N_HEADS + h) * T_SEQ * HEAD_DIM;

    { // Q tile loader: 128 rows, thread -> row tid/2, 32-half chunk
        const int qrow = tid >> 1;
        const int qc   = (tid & 1) * 32;
        const uint32_t qdst = (uint32_t)(qrow * AST + qc) * 2;
        const char* p0 = (const char*)(qh + head_elem + (size_t)(qb * 128 + qrow) * 64 + qc);
#pragma unroll
        for (int c = 0; c < 4; c++)
            CP_ASYNC16(sQh + qdst + c * 16, p0 + c * 16);
        CP_COMMIT();
    }

    // K/V loader: 64 rows, thread -> row tid/4, 16-half (32-byte) chunk
    const int lrow = tid >> 2;
    const int lc   = (tid & 3) * 16;
    const uint32_t sdst = (uint32_t)(lrow * AST + lc) * 2;

    auto load_kv = [&](int stage, int kb) {
        const size_t roff = head_elem + (size_t)(kb * 64 + lrow) * 64 + lc;
        const uint32_t sb = sKV + (uint32_t)stage * (2 * ATILE_B);
        const char* p0 = (const char*)(kh + roff);
        const char* p2 = (const char*)(vh + roff);
#pragma unroll
        for (int c = 0; c < 2; c++) {
            CP_ASYNC16(sb + 0 * ATILE_B + sdst + c * 16, p0 + c * 16);
            CP_ASYNC16(sb + 1 * ATILE_B + sdst + c * 16, p2 + c * 16);
        }
        CP_COMMIT();
    };

    const int nt = 2 * qb + 2;
    load_kv(0, 0);
    load_kv(1, 1);
    CP_WAIT(1);
    __syncthreads();

    uint32_t aQh[4][4];
    {
        const uint32_t a_ld = (uint32_t)((wid * 16 + (lane & 15)) * AST + (lane >> 4) * 8) * 2;
#pragma unroll
        for (int ks = 0; ks < 4; ks++)
            LDSM_X4(aQh[ks][0], aQh[ks][1], aQh[ks][2], aQh[ks][3], sQh + a_ld + ks * 32);
    }

    const uint32_t b_ldK = (uint32_t)(((lane & 7) + ((lane >> 4) << 3)) * AST
                                      + ((lane >> 3) & 1) * 8) * 2;
    const uint32_t v_ld  = (uint32_t)((lane & 15) * AST + ((lane >> 4) << 3)) * 2;

    float O[8][4];
#pragma unroll
    for (int t = 0; t < 8; t++)
#pragma unroll
        for (int e = 0; e < 4; e++) O[t][e] = 0.f;
    float m1 = NEG_INF, m2 = NEG_INF, l1 = 0.f, l2 = 0.f;

    const int rowg1 = qb * 128 + wid * 16 + (lane >> 2);   // global query row (e<2)
    const int colb  = (lane & 3) * 2;

    for (int kt = 0; kt < nt; kt++) {
        if (kt + 2 < nt) load_kv((kt + 2) % 3, kt + 2);

        // Final tile is entirely above-diagonal for warps 0-3 (rows < 128qb+64):
        // skipping QK/softmax/PV there is an exact identity (P=0, c=1).
        const bool active = !(kt == nt - 1 && wid < 4);

        if (active) {
            const uint32_t sb  = sKV + (uint32_t)(kt % 3) * (2 * ATILE_B);
            const uint32_t sKh = sb;
            const uint32_t sVh = sb + ATILE_B;

            float S[8][4];
#pragma unroll
            for (int t = 0; t < 8; t++)
#pragma unroll
                for (int e = 0; e < 4; e++) S[t][e] = 0.f;

            // ---- S = Q K^T : 1-pass
#pragma unroll
            for (int ks = 0; ks < 4; ks++) {
                uint32_t fKh[4][4];
#pragma unroll
                for (int np = 0; np < 4; np++) {
                    const uint32_t off = (uint32_t)(np * 16 * AST) * 2 + ks * 32;
                    LDSM_X4(fKh[np][0], fKh[np][1], fKh[np][2], fKh[np][3], sKh + b_ldK + off);
                }
#pragma unroll
                for (int np = 0; np < 4; np++) {
                    uint32_t b0[2] = {fKh[np][0], fKh[np][1]};
                    MMA_F16(S[2 * np], aQh[ks], b0);
                }
#pragma unroll
                for (int np = 0; np < 4; np++) {
                    uint32_t b1[2] = {fKh[np][2], fKh[np][3]};
                    MMA_F16(S[2 * np + 1], aQh[ks], b1);
                }
            }

            // ---- causal mask (last two tiles cross the diagonal)
            if (kt >= nt - 2) {
#pragma unroll
                for (int t = 0; t < 8; t++) {
#pragma unroll
                    for (int e = 0; e < 4; e++) {
                        const int col = kt * 64 + t * 8 + colb + (e & 1);
                        const int row = rowg1 + (e >> 1) * 8;
                        if (col > row) S[t][e] = NEG_INF;
                    }
                }
            }

            // ---- online softmax (exp2 domain)
            float mx1 = NEG_INF, mx2 = NEG_INF;
#pragma unroll
            for (int t = 0; t < 8; t++) {
                mx1 = fmaxf(mx1, fmaxf(S[t][0], S[t][1]));
                mx2 = fmaxf(mx2, fmaxf(S[t][2], S[t][3]));
            }
            mx1 = fmaxf(mx1, __shfl_xor_sync(0xffffffffu, mx1, 1));
            mx1 = fmaxf(mx1, __shfl_xor_sync(0xffffffffu, mx1, 2));
            mx2 = fmaxf(mx2, __shfl_xor_sync(0xffffffffu, mx2, 1));
            mx2 = fmaxf(mx2, __shfl_xor_sync(0xffffffffu, mx2, 2));

            const float mn1 = fmaxf(m1, mx1);
            const float mn2 = fmaxf(m2, mx2);
            const float c1 = ex2(m1 - mn1);
            const float c2 = ex2(m2 - mn2);
            l1 *= c1; l2 *= c2;
#pragma unroll
            for (int t = 0; t < 8; t++) {
                O[t][0] *= c1; O[t][1] *= c1;
                O[t][2] *= c2; O[t][3] *= c2;
            }
            float rs1 = 0.f, rs2 = 0.f;
#pragma unroll
            for (int t = 0; t < 8; t++) {
                S[t][0] = ex2(S[t][0] - mn1); rs1 += S[t][0];
                S[t][1] = ex2(S[t][1] - mn1); rs1 += S[t][1];
                S[t][2] = ex2(S[t][2] - mn2); rs2 += S[t][2];
                S[t][3] = ex2(S[t][3] - mn2); rs2 += S[t][3];
            }
            rs1 += __shfl_xor_sync(0xffffffffu, rs1, 1);
            rs1 += __shfl_xor_sync(0xffffffffu, rs1, 2);
            rs2 += __shfl_xor_sync(0xffffffffu, rs2, 1);
            rs2 += __shfl_xor_sync(0xffffffffu, rs2, 2);
            l1 += rs1; l2 += rs2;
            m1 = mn1; m2 = mn2;

            // ---- O += P V : 1-pass
#pragma unroll
            for (int ks = 0; ks < 4; ks++) {
                uint32_t aPh[4];
                aPh[0] = pack_f16(S[2 * ks][0],     S[2 * ks][1]);
                aPh[1] = pack_f16(S[2 * ks][2],     S[2 * ks][3]);
                aPh[2] = pack_f16(S[2 * ks + 1][0], S[2 * ks + 1][1]);
                aPh[3] = pack_f16(S[2 * ks + 1][2], S[2 * ks + 1][3]);
                uint32_t fVh[4][4];
#pragma unroll
                for (int np = 0; np < 4; np++) {
                    const uint32_t off = (uint32_t)(ks * 16 * AST) * 2 + np * 32;
                    LDSM_X4_T(fVh[np][0], fVh[np][1], fVh[np][2], fVh[np][3], sVh + v_ld + off);
                }
#pragma unroll
                for (int np = 0; np < 4; np++) {
                    uint32_t b0[2] = {fVh[np][0], fVh[np][1]};
                    MMA_F16(O[2 * np], aPh, b0);
                }
#pragma unroll
                for (int np = 0; np < 4; np++) {
                    uint32_t b1[2] = {fVh[np][2], fVh[np][3]};
                    MMA_F16(O[2 * np + 1], aPh, b1);
                }
            }
        }

        // ---- pipeline advance: single barrier per tile (all warps)
        if (kt + 1 < nt) {
            if (kt + 2 < nt) { CP_WAIT(1); } else { CP_WAIT(0); }
            __syncthreads();
        }
    }

    // ---- epilogue: write f16 into (B,T,D)
    const float inv1 = 1.f / l1;
    const float inv2 = 1.f / l2;
    const size_t obase = (size_t)b * T_SEQ * D_MODEL + (size_t)h * 64;
#pragma unroll
    for (int t = 0; t < 8; t++) {
        const int d = t * 8 + colb;
        size_t i1 = obase + (size_t)rowg1 * D_MODEL + d;
        *(uint32_t*)&oh[i1] = pack_f16(O[t][0] * inv1, O[t][1] * inv1);
        size_t i2 = obase + (size_t)(rowg1 + 8) * D_MODEL + d;
        *(uint32_t*)&oh[i2] = pack_f16(O[t][2] * inv2, O[t][3] * inv2);
    }
}

// ---------------------------------------------------------------------------
extern "C" void kernel_launch(void* const* d_in, const int* in_sizes, int n_in,
                              void* d_out, int out_size)
{
    const float* x  = (const float*)d_in[0];
    const float* Wq = (const float*)d_in[1];
    const float* Wk = (const float*)d_in[2];
    const float* Wv = (const float*)d_in[3];
    const float* Wo = (const float*)d_in[4];

    float* out  = (float*)d_out;
    float* kout = out  + (size_t)M_ROWS * D_MODEL;
    float* vout = kout + (size_t)M_ROWS * D_MODEL;

    __half *xh, *wqh, *wkh, *wvh, *woh;
    __half *qhp, *khp, *vhp, *ahp;
    cudaGetSymbolAddress((void**)&xh,  g_xh);
    cudaGetSymbolAddress((void**)&wqh, g_wqh);
    cudaGetSymbolAddress((void**)&wkh, g_wkh);
    cudaGetSymbolAddress((void**)&wvh, g_wvh);
    cudaGetSymbolAddress((void**)&woh, g_woh);
    cudaGetSymbolAddress((void**)&qhp, g_qh);
    cudaGetSymbolAddress((void**)&khp, g_kh);
    cudaGetSymbolAddress((void**)&vhp, g_vh);
    cudaGetSymbolAddress((void**)&ahp, g_ah);

    cudaFuncSetAttribute(gemm_f16, cudaFuncAttributeMaxDynamicSharedMemorySize,
                         GEMM_SMEM_BYTES);
    cudaFuncSetAttribute(attn_mma, cudaFuncAttributeMaxDynamicSharedMemorySize,
                         ASMEM_BYTES);

    const int nx4 = M_ROWS * D_MODEL / 4;      // 2M, /4 per thread
    const int nw4 = D_MODEL * D_MODEL / 4;     // 256K

    cvt_f16<<<(nx4 / 4 + 255) / 256, 256>>>(x, xh, nx4);
    CvtArgs ca;
    ca.src[0] = Wq; ca.hi[0] = wqh;
    ca.src[1] = Wk; ca.hi[1] = wkh;
    ca.src[2] = Wv; ca.hi[2] = wvh;
    ca.src[3] = Wo; ca.hi[3] = woh;
    cvt_f16m<<<dim3((nw4 / 4 + 255) / 256, 1, 4), 256>>>(ca, nw4);

    // ---- merged QKV GEMM (grid.z: 0=Q, 1=K, 2=V; all 1-pass)
    GemmArgs qkv;
    qkv.Ah = xh;
    qkv.Bh[0] = wqh;
    qkv.Bh[1] = wkh;
    qkv.Bh[2] = wvh;
    qkv.Cf[0] = nullptr; qkv.Cf[1] = kout; qkv.Cf[2] = vout;
    qkv.Ch[0] = qhp;     qkv.Ch[1] = khp;  qkv.Ch[2] = vhp;
    qkv.scale[0] = 0.125f * 1.44269504f;   // fold 1/sqrt(hd) and log2(e)
    qkv.scale[1] = 1.f; qkv.scale[2] = 1.f;
    qkv.split = 1;
    gemm_f16<<<dim3(D_MODEL / BN, M_ROWS / BM, 3), 256, GEMM_SMEM_BYTES>>>(qkv);

    attn_mma<<<dim3(T_SEQ / 128, N_HEADS, B_SIZE), 256, ASMEM_BYTES>>>(
        qhp, khp, vhp, ahp);

    // ---- O projection: 1-pass, fp32 output
    GemmArgs og;
    og.Ah = ahp;
    og.Bh[0] = woh;
    og.Cf[0] = out; og.Ch[0] = nullptr;
    og.scale[0] = 1.f; og.split = 0;
    og.Bh[1] = og.Bh[2] = nullptr;
    og.Cf[1] = og.Cf[2] = nullptr; og.Ch[1] = og.Ch[2] = nullptr;
    og.scale[1] = og.scale[2] = 1.f;
    gemm_f16<<<dim3(D_MODEL / BN, M_ROWS / BM, 1), 256, GEMM_SMEM_BYTES>>>(og);
}

// round 15
// speedup vs baseline: 1.0966x; 1.0966x over previous
#include <cuda_runtime.h>
#include <cuda_fp16.h>
#include <cstdint>
#include <math.h>

#define D_MODEL  1024
#define N_HEADS  16
#define HEAD_DIM 64
#define B_SIZE   4
#define T_SEQ    2048
#define M_ROWS   (B_SIZE * T_SEQ)   // 8192
#define KDIM     1024

#define NEG_INF  (__int_as_float(0xff800000))

// ---------------------------------------------------------------------------
// Scratch (device globals: no allocations allowed)
// ---------------------------------------------------------------------------
__device__ __half g_xh[(size_t)M_ROWS * D_MODEL];
__device__ __half g_wqh[(size_t)D_MODEL * D_MODEL];
__device__ __half g_wkh[(size_t)D_MODEL * D_MODEL];
__device__ __half g_wvh[(size_t)D_MODEL * D_MODEL];
__device__ __half g_woh[(size_t)D_MODEL * D_MODEL];

__device__ __half g_qh[(size_t)M_ROWS * D_MODEL];   // (B,H,T,hd), pre-scaled by 0.125*log2e
__device__ __half g_kh[(size_t)M_ROWS * D_MODEL];
__device__ __half g_vh[(size_t)M_ROWS * D_MODEL];
__device__ __half g_ah[(size_t)M_ROWS * D_MODEL];   // attn out (B,T,D)

// ---------------------------------------------------------------------------
// PTX helpers (base ISA only)
// ---------------------------------------------------------------------------
__device__ __forceinline__ uint32_t smem_to_u32(const void* p) {
    uint32_t a;
    asm("{ .reg .u64 t; cvta.to.shared.u64 t, %1; cvt.u32.u64 %0, t; }"
        : "=r"(a) : "l"(p));
    return a;
}

#define CP_ASYNC16(dst, src) \
    asm volatile("cp.async.cg.shared.global [%0], [%1], 16;" :: "r"(dst), "l"(src))
#define CP_COMMIT() asm volatile("cp.async.commit_group;" ::: "memory")
#define CP_WAIT(n)  asm volatile("cp.async.wait_group %0;" :: "n"(n) : "memory")

#define LDSM_X4(r0, r1, r2, r3, addr) \
    asm volatile("ldmatrix.sync.aligned.m8n8.x4.shared.b16 {%0,%1,%2,%3}, [%4];" \
                 : "=r"(r0), "=r"(r1), "=r"(r2), "=r"(r3) : "r"(addr))
#define LDSM_X4_T(r0, r1, r2, r3, addr) \
    asm volatile("ldmatrix.sync.aligned.m8n8.x4.trans.shared.b16 {%0,%1,%2,%3}, [%4];" \
                 : "=r"(r0), "=r"(r1), "=r"(r2), "=r"(r3) : "r"(addr))

#define MMA_F16(c, a, b) \
    asm volatile("mma.sync.aligned.m16n8k16.row.col.f32.f16.f16.f32 " \
                 "{%0,%1,%2,%3}, {%4,%5,%6,%7}, {%8,%9}, {%0,%1,%2,%3};" \
                 : "+f"((c)[0]), "+f"((c)[1]), "+f"((c)[2]), "+f"((c)[3]) \
                 : "r"((a)[0]), "r"((a)[1]), "r"((a)[2]), "r"((a)[3]), \
                   "r"((b)[0]), "r"((b)[1]))

// pack two fp32 -> f16x2 reg: low half = x, high half = y
__device__ __forceinline__ uint32_t pack_f16(float x, float y) {
    uint32_t r;
    asm("cvt.rn.f16x2.f32 %0, %1, %2;" : "=r"(r) : "f"(y), "f"(x));
    return r;
}
// hardware exp2
__device__ __forceinline__ float ex2(float x) {
    float r;
    asm("ex2.approx.ftz.f32 %0, %1;" : "=f"(r) : "f"(x));
    return r;
}

// ---------------------------------------------------------------------------
// fp32 -> f16 converters (R13 versions)
// ---------------------------------------------------------------------------
__global__ void __launch_bounds__(256) cvt_f16(const float* __restrict__ x,
                                               __half* __restrict__ hi, int n4)
{
    int i = blockIdx.x * blockDim.x + threadIdx.x;
    if (i >= n4) return;
    float4 v = ((const float4*)x)[i];
    ((uint32_t*)hi)[i * 2 + 0] = pack_f16(v.x, v.y);
    ((uint32_t*)hi)[i * 2 + 1] = pack_f16(v.z, v.w);
}

struct CvtArgs {
    const float* src[4];
    __half* hi[4];
};
__global__ void __launch_bounds__(256) cvt_f16m(const CvtArgs a, int n4)
{
    const int z = blockIdx.z;
    const float* x = a.src[z];
    __half* hi = a.hi[z];
    int i = blockIdx.x * blockDim.x + threadIdx.x;
    if (i >= n4) return;
    float4 v = ((const float4*)x)[i];
    ((uint32_t*)hi)[i * 2 + 0] = pack_f16(v.x, v.y);
    ((uint32_t*)hi)[i * 2 + 1] = pack_f16(v.z, v.w);
}

// ---------------------------------------------------------------------------
// mma.sync 1-pass f16 GEMM:  C(8192x1024) = A @ W^T
// BM=64 x BN=128 CTA tile (finer grain -> less wave quantization, 3 CTA/SM).
// 8 warps = 2(m) x 4(n), warp tile 32x32. Same k accumulation order as before
// (bit-identical results).
// ---------------------------------------------------------------------------
#define BM 64
#define BN 128
#define BK 32
#define NKI (KDIM / BK)          // 32
#define SKP 40                   // smem row stride in f16
#define ATILE (BM * SKP * 2)     // 5120 bytes (A tile)
#define BTILE (BN * SKP * 2)     // 10240 bytes (B tile)
#define STAGE_B (ATILE + BTILE)  // 15360
#define GEMM_SMEM_BYTES (3 * STAGE_B)

struct GemmArgs {
    const __half* Ah;
    const __half* Bh[3];
    float*  Cf[3];
    __half* Ch[3];
    float   scale[3];
    int     split;      // 1 -> (B,H,T,hd) output layout
};

__global__ void __launch_bounds__(256, 3) gemm_f16(const GemmArgs args)
{
    extern __shared__ char smem_raw[];
    const uint32_t smem = smem_to_u32(smem_raw);

    const int z = blockIdx.z;
    const __half* Ah = args.Ah;
    const __half* Bh = args.Bh[z];

    const int tid  = threadIdx.x;
    const int wid  = tid >> 5;
    const int lane = tid & 31;
    const int row0 = blockIdx.y * BM;
    const int col0 = blockIdx.x * BN;

    const int m0 = (wid & 1) * 32;    // warp m tile: 32 rows
    const int n0 = (wid >> 1) * 32;   // warp n tile: 32 cols

    // A loader: 64 rows, thread -> row tid/4, 16B chunk (tid&3)
    const int lrowA = tid >> 2;
    const int lchkA = (tid & 3) * 8;               // halves offset
    const size_t a_goff = (size_t)(row0 + lrowA) * KDIM + lchkA;
    const uint32_t sdstA = (uint32_t)(lrowA * SKP + lchkA) * 2;

    // B loader: 128 rows, thread -> row tid/2, 16-half chunk (tid&1)
    const int lrowB = tid >> 1;
    const int lcolB = (tid & 1) * 16;
    const size_t b_goff = (size_t)(col0 + lrowB) * KDIM + lcolB;
    const uint32_t sdstB = (uint32_t)(lrowB * SKP + lcolB) * 2;

    auto load_stage = [&](int stage, int kt) {
        const uint32_t sb = smem + (uint32_t)stage * STAGE_B;
        const size_t ko = (size_t)kt * BK;
        const char* s0 = (const char*)(Ah + a_goff + ko);
        const char* s2 = (const char*)(Bh + b_goff + ko);
        CP_ASYNC16(sb + sdstA, s0);
#pragma unroll
        for (int c = 0; c < 2; c++)
            CP_ASYNC16(sb + ATILE + sdstB + c * 16, s2 + c * 16);
        CP_COMMIT();
    };

    const uint32_t a_ld = (uint32_t)((m0 + (lane & 15)) * SKP + (lane >> 4) * 8) * 2;
    const uint32_t b_ld = (uint32_t)((n0 + (lane & 7) + ((lane >> 4) << 3)) * SKP
                                     + (((lane >> 3) & 1) << 3)) * 2;

    float acc[2][4][4];
#pragma unroll
    for (int i = 0; i < 2; i++)
#pragma unroll
        for (int j = 0; j < 4; j++)
#pragma unroll
            for (int r = 0; r < 4; r++) acc[i][j][r] = 0.f;

    load_stage(0, 0);
    load_stage(1, 1);

    for (int kt = 0; kt < NKI; kt++) {
        if (kt + 1 < NKI) { CP_WAIT(1); } else { CP_WAIT(0); }
        __syncthreads();
        if (kt + 2 < NKI) load_stage((kt + 2) % 3, kt + 2);

        const uint32_t sb  = smem + (uint32_t)(kt % 3) * STAGE_B;
        const uint32_t sAh = sb;
        const uint32_t sBh = sb + ATILE;

#pragma unroll
        for (int ks = 0; ks < 2; ks++) {
            const uint32_t kso = (uint32_t)(ks * 16) * 2;
            uint32_t fAh[2][4];
            uint32_t fBh[4][2];
#pragma unroll
            for (int am = 0; am < 2; am++) {
                const uint32_t off = (uint32_t)(am * 16 * SKP) * 2 + kso;
                LDSM_X4(fAh[am][0], fAh[am][1], fAh[am][2], fAh[am][3], sAh + a_ld + off);
            }
#pragma unroll
            for (int bp = 0; bp < 2; bp++) {
                const uint32_t off = (uint32_t)(bp * 16 * SKP) * 2 + kso;
                LDSM_X4(fBh[2 * bp][0], fBh[2 * bp][1], fBh[2 * bp + 1][0], fBh[2 * bp + 1][1],
                        sBh + b_ld + off);
            }
#pragma unroll
            for (int am = 0; am < 2; am++)
#pragma unroll
                for (int na = 0; na < 4; na++)
                    MMA_F16(acc[am][na], fAh[am], fBh[na]);
        }
    }

    float* Cf = args.Cf[z];
    __half* Ch = args.Ch[z];
    const float scale = args.scale[z];
    const int split = args.split;

    const int lr4 = lane >> 2;
    const int lc2 = (lane & 3) * 2;
#pragma unroll
    for (int am = 0; am < 2; am++) {
        const int mA = row0 + m0 + am * 16 + lr4;
#pragma unroll
        for (int na = 0; na < 4; na++) {
            const int n = col0 + n0 + na * 8 + lc2;
#pragma unroll
            for (int half_ = 0; half_ < 2; half_++) {
                const int m = mA + half_ * 8;
                float vx = acc[am][na][half_ * 2 + 0] * scale;
                float vy = acc[am][na][half_ * 2 + 1] * scale;
                size_t idx;
                if (split) {
                    const int bb = m >> 11, t = m & 2047;
                    const int hh = n >> 6, d = n & 63;
                    idx = (((size_t)bb * N_HEADS + hh) * T_SEQ + t) * HEAD_DIM + d;
                } else {
                    idx = (size_t)m * D_MODEL + n;
                }
                if (Cf) *(float2*)&Cf[idx] = make_float2(vx, vy);
                if (Ch) *(uint32_t*)&Ch[idx] = pack_f16(vx, vy);
            }
        }
    }
}

// ---------------------------------------------------------------------------
// mma.sync flash attention, causal (EXACT R13 version — 471.8us kernel).
// BQ=128 (8 warps x m16), BKV=64, 256 thr; exp2-domain softmax;
// 3-stage pipeline, one barrier per tile.
// ---------------------------------------------------------------------------
#define AST 72                        // smem row stride (f16 elems)
#define KTILE_B (64 * AST * 2)        // 9216 bytes (64-row K/V tile)
#define QTILE_B (128 * AST * 2)       // 18432 bytes (128-row Q tile)
#define ASMEM_BYTES (QTILE_B + 6 * KTILE_B)   // Q + 3 stages x {Kh,Vh}

__global__ void __launch_bounds__(256, 2) attn_mma(
    const __half* __restrict__ qh,
    const __half* __restrict__ kh,
    const __half* __restrict__ vh,
    __half* __restrict__ oh)
{
    extern __shared__ char smem_raw[];
    const uint32_t smem = smem_to_u32(smem_raw);
    const uint32_t sQh = smem;
    const uint32_t sKV = smem + QTILE_B;

    const int tid  = threadIdx.x;
    const int wid  = tid >> 5;
    const int lane = tid & 31;
    const int qb = gridDim.x - 1 - blockIdx.x;   // heaviest tiles first
    const int h = blockIdx.y, b = blockIdx.z;
    const size_t head_elem = ((size_t)b * N_HEADS + h) * T_SEQ * HEAD_DIM;

    { // Q tile loader: 128 rows, thread -> row tid/2, 32-half chunk
        const int qrow = tid >> 1;
        const int qc   = (tid & 1) * 32;
        const uint32_t qdst = (uint32_t)(qrow * AST + qc) * 2;
        const char* p0 = (const char*)(qh + head_elem + (size_t)(qb * 128 + qrow) * 64 + qc);
#pragma unroll
        for (int c = 0; c < 4; c++)
            CP_ASYNC16(sQh + qdst + c * 16, p0 + c * 16);
        CP_COMMIT();
    }

    // K/V loader: 64 rows, thread -> row tid/4, 16-half (32-byte) chunk
    const int lrow = tid >> 2;
    const int lc   = (tid & 3) * 16;
    const uint32_t sdst = (uint32_t)(lrow * AST + lc) * 2;

    auto load_kv = [&](int stage, int kb) {
        const size_t roff = head_elem + (size_t)(kb * 64 + lrow) * 64 + lc;
        const uint32_t sb = sKV + (uint32_t)stage * (2 * KTILE_B);
        const char* p0 = (const char*)(kh + roff);
        const char* p2 = (const char*)(vh + roff);
#pragma unroll
        for (int c = 0; c < 2; c++) {
            CP_ASYNC16(sb + 0 * KTILE_B + sdst + c * 16, p0 + c * 16);
            CP_ASYNC16(sb + 1 * KTILE_B + sdst + c * 16, p2 + c * 16);
        }
        CP_COMMIT();
    };

    const int nt = 2 * qb + 2;
    load_kv(0, 0);
    load_kv(1, 1);
    CP_WAIT(1);
    __syncthreads();

    uint32_t aQh[4][4];
    {
        const uint32_t a_ld = (uint32_t)((wid * 16 + (lane & 15)) * AST + (lane >> 4) * 8) * 2;
#pragma unroll
        for (int ks = 0; ks < 4; ks++)
            LDSM_X4(aQh[ks][0], aQh[ks][1], aQh[ks][2], aQh[ks][3], sQh + a_ld + ks * 32);
    }

    const uint32_t b_ldK = (uint32_t)(((lane & 7) + ((lane >> 4) << 3)) * AST
                                      + ((lane >> 3) & 1) * 8) * 2;
    const uint32_t v_ld  = (uint32_t)((lane & 15) * AST + ((lane >> 4) << 3)) * 2;

    float O[8][4];
#pragma unroll
    for (int t = 0; t < 8; t++)
#pragma unroll
        for (int e = 0; e < 4; e++) O[t][e] = 0.f;
    float m1 = NEG_INF, m2 = NEG_INF, l1 = 0.f, l2 = 0.f;

    const int rowg1 = qb * 128 + wid * 16 + (lane >> 2);   // global query row (e<2)
    const int colb  = (lane & 3) * 2;

    for (int kt = 0; kt < nt; kt++) {
        if (kt + 2 < nt) load_kv((kt + 2) % 3, kt + 2);

        const uint32_t sb  = sKV + (uint32_t)(kt % 3) * (2 * KTILE_B);
        const uint32_t sKh = sb;
        const uint32_t sVh = sb + KTILE_B;

        float S[8][4];
#pragma unroll
        for (int t = 0; t < 8; t++)
#pragma unroll
            for (int e = 0; e < 4; e++) S[t][e] = 0.f;

        // ---- S = Q K^T : 1-pass
#pragma unroll
        for (int ks = 0; ks < 4; ks++) {
            uint32_t fKh[4][4];
#pragma unroll
            for (int np = 0; np < 4; np++) {
                const uint32_t off = (uint32_t)(np * 16 * AST) * 2 + ks * 32;
                LDSM_X4(fKh[np][0], fKh[np][1], fKh[np][2], fKh[np][3], sKh + b_ldK + off);
            }
#pragma unroll
            for (int np = 0; np < 4; np++) {
                uint32_t b0[2] = {fKh[np][0], fKh[np][1]};
                MMA_F16(S[2 * np], aQh[ks], b0);
            }
#pragma unroll
            for (int np = 0; np < 4; np++) {
                uint32_t b1[2] = {fKh[np][2], fKh[np][3]};
                MMA_F16(S[2 * np + 1], aQh[ks], b1);
            }
        }

        // ---- causal mask (last two tiles cross the diagonal for this CTA)
        if (kt >= nt - 2) {
#pragma unroll
            for (int t = 0; t < 8; t++) {
#pragma unroll
                for (int e = 0; e < 4; e++) {
                    const int col = kt * 64 + t * 8 + colb + (e & 1);
                    const int row = rowg1 + (e >> 1) * 8;
                    if (col > row) S[t][e] = NEG_INF;
                }
            }
        }

        // ---- online softmax (exp2 domain)
        float mx1 = NEG_INF, mx2 = NEG_INF;
#pragma unroll
        for (int t = 0; t < 8; t++) {
            mx1 = fmaxf(mx1, fmaxf(S[t][0], S[t][1]));
            mx2 = fmaxf(mx2, fmaxf(S[t][2], S[t][3]));
        }
        mx1 = fmaxf(mx1, __shfl_xor_sync(0xffffffffu, mx1, 1));
        mx1 = fmaxf(mx1, __shfl_xor_sync(0xffffffffu, mx1, 2));
        mx2 = fmaxf(mx2, __shfl_xor_sync(0xffffffffu, mx2, 1));
        mx2 = fmaxf(mx2, __shfl_xor_sync(0xffffffffu, mx2, 2));

        const float mn1 = fmaxf(m1, mx1);
        const float mn2 = fmaxf(m2, mx2);
        const float c1 = ex2(m1 - mn1);
        const float c2 = ex2(m2 - mn2);
        l1 *= c1; l2 *= c2;
#pragma unroll
        for (int t = 0; t < 8; t++) {
            O[t][0] *= c1; O[t][1] *= c1;
            O[t][2] *= c2; O[t][3] *= c2;
        }
        float rs1 = 0.f, rs2 = 0.f;
#pragma unroll
        for (int t = 0; t < 8; t++) {
            S[t][0] = ex2(S[t][0] - mn1); rs1 += S[t][0];
            S[t][1] = ex2(S[t][1] - mn1); rs1 += S[t][1];
            S[t][2] = ex2(S[t][2] - mn2); rs2 += S[t][2];
            S[t][3] = ex2(S[t][3] - mn2); rs2 += S[t][3];
        }
        rs1 += __shfl_xor_sync(0xffffffffu, rs1, 1);
        rs1 += __shfl_xor_sync(0xffffffffu, rs1, 2);
        rs2 += __shfl_xor_sync(0xffffffffu, rs2, 1);
        rs2 += __shfl_xor_sync(0xffffffffu, rs2, 2);
        l1 += rs1; l2 += rs2;
        m1 = mn1; m2 = mn2;

        // ---- O += P V : 1-pass (P hi x V hi)
#pragma unroll
        for (int ks = 0; ks < 4; ks++) {
            uint32_t aPh[4];
            aPh[0] = pack_f16(S[2 * ks][0],     S[2 * ks][1]);
            aPh[1] = pack_f16(S[2 * ks][2],     S[2 * ks][3]);
            aPh[2] = pack_f16(S[2 * ks + 1][0], S[2 * ks + 1][1]);
            aPh[3] = pack_f16(S[2 * ks + 1][2], S[2 * ks + 1][3]);
            uint32_t fVh[4][4];
#pragma unroll
            for (int np = 0; np < 4; np++) {
                const uint32_t off = (uint32_t)(ks * 16 * AST) * 2 + np * 32;
                LDSM_X4_T(fVh[np][0], fVh[np][1], fVh[np][2], fVh[np][3], sVh + v_ld + off);
            }
#pragma unroll
            for (int np = 0; np < 4; np++) {
                uint32_t b0[2] = {fVh[np][0], fVh[np][1]};
                MMA_F16(O[2 * np], aPh, b0);
            }
#pragma unroll
            for (int np = 0; np < 4; np++) {
                uint32_t b1[2] = {fVh[np][2], fVh[np][3]};
                MMA_F16(O[2 * np + 1], aPh, b1);
            }
        }

        // ---- pipeline advance: single barrier per tile
        if (kt + 1 < nt) {
            if (kt + 2 < nt) { CP_WAIT(1); } else { CP_WAIT(0); }
            __syncthreads();
        }
    }

    // ---- epilogue: write f16 into (B,T,D)
    const float inv1 = 1.f / l1;
    const float inv2 = 1.f / l2;
    const size_t obase = (size_t)b * T_SEQ * D_MODEL + (size_t)h * 64;
#pragma unroll
    for (int t = 0; t < 8; t++) {
        const int d = t * 8 + colb;
        size_t i1 = obase + (size_t)rowg1 * D_MODEL + d;
        *(uint32_t*)&oh[i1] = pack_f16(O[t][0] * inv1, O[t][1] * inv1);
        size_t i2 = obase + (size_t)(rowg1 + 8) * D_MODEL + d;
        *(uint32_t*)&oh[i2] = pack_f16(O[t][2] * inv2, O[t][3] * inv2);
    }
}

// ---------------------------------------------------------------------------
extern "C" void kernel_launch(void* const* d_in, const int* in_sizes, int n_in,
                              void* d_out, int out_size)
{
    const float* x  = (const float*)d_in[0];
    const float* Wq = (const float*)d_in[1];
    const float* Wk = (const float*)d_in[2];
    const float* Wv = (const float*)d_in[3];
    const float* Wo = (const float*)d_in[4];

    float* out  = (float*)d_out;
    float* kout = out  + (size_t)M_ROWS * D_MODEL;
    float* vout = kout + (size_t)M_ROWS * D_MODEL;

    __half *xh, *wqh, *wkh, *wvh, *woh;
    __half *qhp, *khp, *vhp, *ahp;
    cudaGetSymbolAddress((void**)&xh,  g_xh);
    cudaGetSymbolAddress((void**)&wqh, g_wqh);
    cudaGetSymbolAddress((void**)&wkh, g_wkh);
    cudaGetSymbolAddress((void**)&wvh, g_wvh);
    cudaGetSymbolAddress((void**)&woh, g_woh);
    cudaGetSymbolAddress((void**)&qhp, g_qh);
    cudaGetSymbolAddress((void**)&khp, g_kh);
    cudaGetSymbolAddress((void**)&vhp, g_vh);
    cudaGetSymbolAddress((void**)&ahp, g_ah);

    cudaFuncSetAttribute(gemm_f16, cudaFuncAttributeMaxDynamicSharedMemorySize,
                         GEMM_SMEM_BYTES);
    cudaFuncSetAttribute(attn_mma, cudaFuncAttributeMaxDynamicSharedMemorySize,
                         ASMEM_BYTES);

    const int nx4 = M_ROWS * D_MODEL / 4;
    const int nw4 = D_MODEL * D_MODEL / 4;

    cvt_f16<<<(nx4 + 255) / 256, 256>>>(x, xh, nx4);
    CvtArgs ca;
    ca.src[0] = Wq; ca.hi[0] = wqh;
    ca.src[1] = Wk; ca.hi[1] = wkh;
    ca.src[2] = Wv; ca.hi[2] = wvh;
    ca.src[3] = Wo; ca.hi[3] = woh;
    cvt_f16m<<<dim3((nw4 + 255) / 256, 1, 4), 256>>>(ca, nw4);

    // ---- merged QKV GEMM (grid.z: 0=Q, 1=K, 2=V; all 1-pass, BM=64 tiles)
    GemmArgs qkv;
    qkv.Ah = xh;
    qkv.Bh[0] = wqh;
    qkv.Bh[1] = wkh;
    qkv.Bh[2] = wvh;
    qkv.Cf[0] = nullptr; qkv.Cf[1] = kout; qkv.Cf[2] = vout;
    qkv.Ch[0] = qhp;     qkv.Ch[1] = khp;  qkv.Ch[2] = vhp;
    qkv.scale[0] = 0.125f * 1.44269504f;   // fold 1/sqrt(hd) and log2(e)
    qkv.scale[1] = 1.f; qkv.scale[2] = 1.f;
    qkv.split = 1;
    gemm_f16<<<dim3(D_MODEL / BN, M_ROWS / BM, 3), 256, GEMM_SMEM_BYTES>>>(qkv);

    attn_mma<<<dim3(T_SEQ / 128, N_HEADS, B_SIZE), 256, ASMEM_BYTES>>>(
        qhp, khp, vhp, ahp);

    // ---- O projection: 1-pass, fp32 output
    GemmArgs og;
    og.Ah = ahp;
    og.Bh[0] = woh;
    og.Cf[0] = out; og.Ch[0] = nullptr;
    og.scale[0] = 1.f; og.split = 0;
    og.Bh[1] = og.Bh[2] = nullptr;
    og.Cf[1] = og.Cf[2] = nullptr; og.Ch[1] = og.Ch[2] = nullptr;
    og.scale[1] = og.scale[2] = 1.f;
    gemm_f16<<<dim3(D_MODEL / BN, M_ROWS / BM, 1), 256, GEMM_SMEM_BYTES>>>(og);
}